// round 15
// baseline (speedup 1.0000x reference)
#include <cuda_runtime.h>
#include <cstdint>
#include <cstddef>

#define HID 256
#define LIN_DIM 652
#define OUTC 5

// Scratch floats: h0 (N*652) + h + tmp + agg + z (each N*256) + spill (N)
// plus int region for CSR: cnt(N) rowptr(N+1) cursor(N) col(E) part(P)
__device__ __align__(256) float g_scratch[85000000];

// ---------------------------------------------------------------------------
// Conv 3x3 VALID (8->8 ch, 11x11 -> 9x9) + flatten + concat bd_pred + relu
// ---------------------------------------------------------------------------
__global__ __launch_bounds__(288)
void conv_kernel(const float* __restrict__ x, const float* __restrict__ w,
                 const float* __restrict__ cb, const float* __restrict__ bd,
                 float* __restrict__ h0, int N)
{
    __shared__ float sx[4][968];
    __shared__ float sw[576];
    __shared__ float sb[8];
    const int tid = threadIdx.x;
    const int node0 = blockIdx.x * 4;

    for (int i = tid; i < 576; i += 288) sw[i] = w[i];
    if (tid < 8) sb[tid] = cb[tid];
    for (int i = tid; i < 4 * 968; i += 288) {
        int ln = i / 968;
        int off = i - ln * 968;
        int n = node0 + ln;
        sx[ln][off] = (n < N) ? x[(size_t)n * 968 + off] : 0.f;
    }
    __syncthreads();

    const int ln = tid / 72;
    const int t  = tid - ln * 72;
    const int n  = node0 + ln;
    if (n >= N) return;
    const int co = t / 9;
    const int io = t - co * 9;

    float acc[9];
#pragma unroll
    for (int j = 0; j < 9; j++) acc[j] = sb[co];

#pragma unroll
    for (int ci = 0; ci < 8; ci++) {
#pragma unroll
        for (int di = 0; di < 3; di++) {
            const float* xr = &sx[ln][ci * 121 + (io + di) * 11];
            const int wbase = ((co * 8 + ci) * 3 + di) * 3;
            const float w0 = sw[wbase + 0];
            const float w1 = sw[wbase + 1];
            const float w2 = sw[wbase + 2];
            float xv[11];
#pragma unroll
            for (int q = 0; q < 11; q++) xv[q] = xr[q];
#pragma unroll
            for (int j = 0; j < 9; j++)
                acc[j] += xv[j] * w0 + xv[j + 1] * w1 + xv[j + 2] * w2;
        }
    }

    float* op = h0 + (size_t)n * LIN_DIM + co * 81 + io * 9;
#pragma unroll
    for (int j = 0; j < 9; j++) op[j] = fmaxf(acc[j], 0.f);

    if (t < 4)
        h0[(size_t)n * LIN_DIM + 648 + t] = fmaxf(bd[(size_t)n * 4 + t], 0.f);
}

// ---------------------------------------------------------------------------
// Tensor-core GEMM with 2-term bf16 split (hi+lo), fp32 accumulate.
//   C[M,Nout] = A0 @ W0^T [K0] + A1 @ W1^T [K1, optional] + bias
// Block 128x128, BK=16, 8 warps (warp tile 32x64), mma.m16n8k16.bf16.
// acc += Ahi*Bhi + Ahi*Blo + Alo*Bhi  (lo*lo dropped, ~2^-34)
//
// Smem layout pairs k2 and k2+4 into one 8-byte word so fragment loads are
// LDS.64: word[k2&3][r*2 + (k2>>2)]  ->  uint2 {val(k2), val(k2+4)}.
// ---------------------------------------------------------------------------
#define BM 128
#define BN 128
#define SSTR2 272   // 2*128 cols + 16 pad (u32 units)

__device__ __forceinline__ void f32_to_bf16x2_pair(uint32_t& hi, uint32_t& lo,
                                                   float f0, float f1)
{
    uint32_t h;
    asm("cvt.rn.bf16x2.f32 %0, %1, %2;" : "=r"(h) : "f"(f1), "f"(f0));
    const float h0 = __uint_as_float(h << 16);
    const float h1 = __uint_as_float(h & 0xffff0000u);
    const float s0 = f0 - h0;
    const float s1 = f1 - h1;
    asm("cvt.rn.bf16x2.f32 %0, %1, %2;" : "=r"(lo) : "f"(s1), "f"(s0));
    hi = h;
}

__device__ __forceinline__ void mma_bf16(float* c, const uint32_t* a, const uint32_t* b)
{
    asm volatile(
        "mma.sync.aligned.m16n8k16.row.col.f32.bf16.bf16.f32 "
        "{%0,%1,%2,%3}, {%4,%5,%6,%7}, {%8,%9}, {%0,%1,%2,%3};"
        : "+f"(c[0]), "+f"(c[1]), "+f"(c[2]), "+f"(c[3])
        : "r"(a[0]), "r"(a[1]), "r"(a[2]), "r"(a[3]), "r"(b[0]), "r"(b[1]));
}

__global__ __launch_bounds__(256)
void mma_gemm(const float* __restrict__ A0, const float* __restrict__ W0, int K0,
              const float* __restrict__ A1, const float* __restrict__ W1, int K1,
              const float* __restrict__ bias,
              float* __restrict__ C, int M, int Nout)
{
    __shared__ uint32_t AsH[2][4][SSTR2];
    __shared__ uint32_t AsL[2][4][SSTR2];
    __shared__ uint32_t BsH[2][4][SSTR2];
    __shared__ uint32_t BsL[2][4][SSTR2];

    const int tid  = threadIdx.x;
    const int row0 = blockIdx.y * BM;
    const int col0 = blockIdx.x * BN;
    const int wid  = tid >> 5;
    const int lane = tid & 31;
    const int wm   = (wid & 3) * 32;
    const int wn   = (wid >> 2) * 64;
    const int g    = lane >> 2;
    const int tg   = lane & 3;

    float acc[2][8][4];
#pragma unroll
    for (int t = 0; t < 2; t++)
#pragma unroll
        for (int u = 0; u < 8; u++)
#pragma unroll
            for (int q = 0; q < 4; q++) acc[t][u][q] = 0.f;

    const int nc0 = (K0 + 15) >> 4;
    const int nc1 = (K1 + 15) >> 4;
    const int nch = nc0 + nc1;

    float2 ra[4], rb[4];

    auto load_global = [&](int c) {
        const bool seg1 = (c >= nc0);
        const float* A = seg1 ? A1 : A0;
        const float* W = seg1 ? W1 : W0;
        const int K  = seg1 ? K1 : K0;
        const int k0 = (seg1 ? (c - nc0) : c) << 4;
#pragma unroll
        for (int i = 0; i < 4; i++) {
            const int p  = tid + i * 256;
            const int r  = p >> 3;
            const int k2 = p & 7;
            const int k  = k0 + (k2 << 1);
            float2 va = make_float2(0.f, 0.f);
            const int grow = row0 + r;
            if (grow < M && k < K)
                va = *(const float2*)&A[(size_t)grow * K + k];
            ra[i] = va;
            float2 vb = make_float2(0.f, 0.f);
            if (k < K)
                vb = *(const float2*)&W[(size_t)(col0 + r) * K + k];
            rb[i] = vb;
        }
    };

    auto convert_store = [&](int b) {
#pragma unroll
        for (int i = 0; i < 4; i++) {
            const int p   = tid + i * 256;
            const int r   = p >> 3;
            const int k2  = p & 7;
            const int row = k2 & 3;
            const int col = r * 2 + (k2 >> 2);
            uint32_t hi, lo;
            f32_to_bf16x2_pair(hi, lo, ra[i].x, ra[i].y);
            AsH[b][row][col] = hi;
            AsL[b][row][col] = lo;
            f32_to_bf16x2_pair(hi, lo, rb[i].x, rb[i].y);
            BsH[b][row][col] = hi;
            BsL[b][row][col] = lo;
        }
    };

    auto compute = [&](int b) {
        uint32_t ah[2][4], al[2][4], bh[8][2], bl[8][2];
#pragma unroll
        for (int t = 0; t < 2; t++) {
            const int base = wm + t * 16 + g;
            // uint2 {k2=tg, k2=tg+4} at row 'base' / 'base+8'
            const uint2 h0 = *(const uint2*)&AsH[b][tg][base * 2];
            const uint2 h1 = *(const uint2*)&AsH[b][tg][(base + 8) * 2];
            ah[t][0] = h0.x; ah[t][1] = h1.x; ah[t][2] = h0.y; ah[t][3] = h1.y;
            const uint2 l0 = *(const uint2*)&AsL[b][tg][base * 2];
            const uint2 l1 = *(const uint2*)&AsL[b][tg][(base + 8) * 2];
            al[t][0] = l0.x; al[t][1] = l1.x; al[t][2] = l0.y; al[t][3] = l1.y;
        }
#pragma unroll
        for (int u = 0; u < 8; u++) {
            const int bn = wn + u * 8 + g;
            const uint2 h = *(const uint2*)&BsH[b][tg][bn * 2];
            bh[u][0] = h.x; bh[u][1] = h.y;
            const uint2 l = *(const uint2*)&BsL[b][tg][bn * 2];
            bl[u][0] = l.x; bl[u][1] = l.y;
        }
#pragma unroll
        for (int t = 0; t < 2; t++)
#pragma unroll
            for (int u = 0; u < 8; u++) {
                mma_bf16(acc[t][u], ah[t], bh[u]);
                mma_bf16(acc[t][u], ah[t], bl[u]);
                mma_bf16(acc[t][u], al[t], bh[u]);
            }
    };

    load_global(0);
    convert_store(0);
    __syncthreads();

    int buf = 0;
    for (int c = 1; c < nch; c++) {
        load_global(c);
        compute(buf);
        convert_store(buf ^ 1);
        __syncthreads();
        buf ^= 1;
    }
    compute(buf);

#pragma unroll
    for (int t = 0; t < 2; t++) {
        const int r_ = row0 + wm + t * 16 + g;
#pragma unroll
        for (int u = 0; u < 8; u++) {
            const int c_ = col0 + wn + u * 8 + 2 * tg;
            float b0 = 0.f, b1 = 0.f;
            if (bias) { b0 = bias[c_]; b1 = bias[c_ + 1]; }
            if (r_ < M) {
                float2 v = make_float2(acc[t][u][0] + b0, acc[t][u][1] + b1);
                *(float2*)&C[(size_t)r_ * Nout + c_] = v;
            }
            if (r_ + 8 < M) {
                float2 v = make_float2(acc[t][u][2] + b0, acc[t][u][3] + b1);
                *(float2*)&C[(size_t)(r_ + 8) * Nout + c_] = v;
            }
        }
    }
}

// ---------------------------------------------------------------------------
// CSR build: histogram -> 3-phase exclusive scan -> cursor fill
// ---------------------------------------------------------------------------
__global__ void hist_kernel(const int* __restrict__ ei, int* __restrict__ cnt,
                            int E, int N)
{
    const int e = blockIdx.x * blockDim.x + threadIdx.x;
    if (e >= E) return;
    const int d = ei[E + e];
    if ((unsigned)d < (unsigned)N) atomicAdd(&cnt[d], 1);
}

__global__ void scan_pass1(const int* __restrict__ cnt, int* __restrict__ part, int N)
{
    __shared__ int sh[256];
    const int b = blockIdx.x, t = threadIdx.x;
    const int base = b * 1024;
    int s = 0;
#pragma unroll
    for (int i = 0; i < 4; i++) {
        const int idx = base + t * 4 + i;
        if (idx < N) s += cnt[idx];
    }
    sh[t] = s;
    __syncthreads();
    for (int off = 128; off; off >>= 1) {
        if (t < off) sh[t] += sh[t + off];
        __syncthreads();
    }
    if (t == 0) part[b] = sh[0];
}

__global__ void scan_pass2(int* __restrict__ part, int P,
                           int* __restrict__ rowptr, int N, int E)
{
    const int t = threadIdx.x;
    if (P <= 64) {
        __shared__ int sh[64];
        int v = (t < P) ? part[t] : 0;
        sh[t] = v;
        __syncthreads();
        for (int off = 1; off < 64; off <<= 1) {
            const int x = (t >= off) ? sh[t - off] : 0;
            __syncthreads();
            sh[t] += x;
            __syncthreads();
        }
        if (t < P) part[t] = sh[t] - v;
        if (t == 0) rowptr[N] = E;
    } else if (t == 0) {
        int run = 0;
        for (int i = 0; i < P; i++) { const int v = part[i]; part[i] = run; run += v; }
        rowptr[N] = E;
    }
}

__global__ void scan_pass3(const int* __restrict__ cnt, const int* __restrict__ part,
                           int* __restrict__ rowptr, int N)
{
    __shared__ int sh[256];
    const int b = blockIdx.x, t = threadIdx.x;
    const int base = b * 1024;
    int v[4];
    int s = 0;
#pragma unroll
    for (int i = 0; i < 4; i++) {
        const int idx = base + t * 4 + i;
        v[i] = (idx < N) ? cnt[idx] : 0;
        s += v[i];
    }
    sh[t] = s;
    __syncthreads();
    for (int off = 1; off < 256; off <<= 1) {
        const int x = (t >= off) ? sh[t - off] : 0;
        __syncthreads();
        sh[t] += x;
        __syncthreads();
    }
    int excl = (t ? sh[t - 1] : 0) + part[b];
#pragma unroll
    for (int i = 0; i < 4; i++) {
        const int idx = base + t * 4 + i;
        if (idx < N) { rowptr[idx] = excl; excl += v[i]; }
    }
}

__global__ void fill_col(const int* __restrict__ ei, const int* __restrict__ rowptr,
                         int* __restrict__ cursor, int* __restrict__ col, int E, int N)
{
    const int e = blockIdx.x * blockDim.x + threadIdx.x;
    if (e >= E) return;
    const int s = ei[e];
    const int d = ei[E + e];
    if ((unsigned)s >= (unsigned)N || (unsigned)d >= (unsigned)N) return;
    const int pos = rowptr[d] + atomicAdd(&cursor[d], 1);
    col[pos] = s;
}

// ---------------------------------------------------------------------------
// CSR gather aggregation (float4-vectorized). 4 rows/block, 64 thr/row.
// ---------------------------------------------------------------------------
__global__ __launch_bounds__(256)
void gather_kernel(const float* __restrict__ feat,
                   const int* __restrict__ rowptr,
                   const int* __restrict__ col,
                   float* __restrict__ out, int mode, int N)
{
    const int r = blockIdx.x * 4 + (threadIdx.x >> 6);
    const int t = threadIdx.x & 63;
    if (r >= N) return;
    const int beg = rowptr[r], end = rowptr[r + 1];

    float4 s = make_float4(0.f, 0.f, 0.f, 0.f);
    int e = beg;
    for (; e + 1 < end; e += 2) {
        const int s0 = col[e], s1 = col[e + 1];
        const float4 v0 = ((const float4*)(feat + (size_t)s0 * HID))[t];
        const float4 v1 = ((const float4*)(feat + (size_t)s1 * HID))[t];
        s.x += v0.x + v1.x;
        s.y += v0.y + v1.y;
        s.z += v0.z + v1.z;
        s.w += v0.w + v1.w;
    }
    if (e < end) {
        const float4 v = ((const float4*)(feat + (size_t)col[e] * HID))[t];
        s.x += v.x; s.y += v.y; s.z += v.z; s.w += v.w;
    }

    float4* op = (float4*)(out + (size_t)r * HID) + t;
    if (mode) {
        const int d = end - beg;
        const float inv = 1.f / (float)(d > 0 ? d : 1);
        *op = make_float4(s.x * inv, s.y * inv, s.z * inv, s.w * inv);
    } else {
        const float4 o = *op;
        *op = make_float4(o.x + s.x, o.y + s.y, o.z + s.z, o.w + s.w);
    }
}

// ---------------------------------------------------------------------------
// relu (+ optional layernorm over HID=256). One block (256 threads) per row.
// ---------------------------------------------------------------------------
__global__ void relu_ln_kernel(const float* __restrict__ in, float* __restrict__ out,
                               const float* __restrict__ gamma, const float* __restrict__ beta,
                               int doLN)
{
    const int r = blockIdx.x;
    const int t = threadIdx.x;
    const size_t idx = (size_t)r * HID + t;
    const float v = fmaxf(in[idx], 0.f);
    if (!doLN) { out[idx] = v; return; }

    float s = v, s2 = v * v;
#pragma unroll
    for (int off = 16; off; off >>= 1) {
        s  += __shfl_xor_sync(0xffffffffu, s, off);
        s2 += __shfl_xor_sync(0xffffffffu, s2, off);
    }
    __shared__ float sh[16];
    const int wid = t >> 5, lane = t & 31;
    if (lane == 0) { sh[wid] = s; sh[8 + wid] = s2; }
    __syncthreads();
    if (t == 0) {
        float S = 0.f, S2 = 0.f;
#pragma unroll
        for (int i = 0; i < 8; i++) { S += sh[i]; S2 += sh[8 + i]; }
        const float mu = S * (1.f / HID);
        const float var = S2 * (1.f / HID) - mu * mu;
        sh[0] = mu;
        sh[1] = rsqrtf(var + 1e-5f);
    }
    __syncthreads();
    const float mu = sh[0], rstd = sh[1];
    out[idx] = (v - mu) * rstd * gamma[t] + beta[t];
}

// ---------------------------------------------------------------------------
// Head: logits[5] = z @ mp2_w^T + b, then log_softmax. One warp per row.
// ---------------------------------------------------------------------------
__global__ void head_kernel(const float* __restrict__ z, const float* __restrict__ w2,
                            const float* __restrict__ b2, float* __restrict__ out, int N)
{
    const int row = blockIdx.x * 8 + (threadIdx.x >> 5);
    const int lane = threadIdx.x & 31;
    if (row >= N) return;
    const float* zr = z + (size_t)row * HID;
    float a0 = 0, a1 = 0, a2 = 0, a3 = 0, a4 = 0;
    for (int k = lane; k < HID; k += 32) {
        const float v = zr[k];
        a0 += v * w2[k];
        a1 += v * w2[256 + k];
        a2 += v * w2[512 + k];
        a3 += v * w2[768 + k];
        a4 += v * w2[1024 + k];
    }
#pragma unroll
    for (int off = 16; off; off >>= 1) {
        a0 += __shfl_xor_sync(0xffffffffu, a0, off);
        a1 += __shfl_xor_sync(0xffffffffu, a1, off);
        a2 += __shfl_xor_sync(0xffffffffu, a2, off);
        a3 += __shfl_xor_sync(0xffffffffu, a3, off);
        a4 += __shfl_xor_sync(0xffffffffu, a4, off);
    }
    if (lane == 0) {
        float l[5] = {a0 + b2[0], a1 + b2[1], a2 + b2[2], a3 + b2[3], a4 + b2[4]};
        float mx = l[0];
#pragma unroll
        for (int o = 1; o < 5; o++) mx = fmaxf(mx, l[o]);
        float se = 0.f;
#pragma unroll
        for (int o = 0; o < 5; o++) se += expf(l[o] - mx);
        const float lse = mx + logf(se);
#pragma unroll
        for (int o = 0; o < 5; o++) out[(size_t)row * 5 + o] = l[o] - lse;
    }
}

// ---------------------------------------------------------------------------
extern "C" void kernel_launch(void* const* d_in, const int* in_sizes, int n_in,
                              void* d_out, int out_size)
{
    const float* x          = (const float*)d_in[0];
    const float* bd         = (const float*)d_in[1];
    const int*   ei         = (const int*)d_in[2];   // int64 downcast to int32 by harness
    const float* conv_w     = (const float*)d_in[3];
    const float* conv_b     = (const float*)d_in[4];
    const float* lin_w      = (const float*)d_in[5];
    const float* lin_b      = (const float*)d_in[6];
    const float* lin_self_w = (const float*)d_in[7];
    const float* lin_self_b = (const float*)d_in[8];
    const float* sage_l_w   = (const float*)d_in[9];
    const float* sage_l_b   = (const float*)d_in[10];
    const float* sage_r_w   = (const float*)d_in[11];
    const float* ln_g       = (const float*)d_in[12];
    const float* ln_beta    = (const float*)d_in[13];
    const float* mp1_w      = (const float*)d_in[14];
    const float* mp1_b      = (const float*)d_in[15];
    const float* mp2_w      = (const float*)d_in[16];
    const float* mp2_b      = (const float*)d_in[17];

    const int N = in_sizes[1] / 4;   // bd_pred is [N,4]
    const int E = in_sizes[2] / 2;   // edge_index is [2,E]

    float* base = nullptr;
    cudaGetSymbolAddress((void**)&base, g_scratch);
    float* h0     = base;
    float* h      = h0  + (size_t)N * LIN_DIM;
    float* tmp    = h   + (size_t)N * HID;
    float* agg    = tmp + (size_t)N * HID;
    float* z      = agg + (size_t)N * HID;
    float* fend   = z   + (size_t)N * HID;

    int* cnt    = (int*)(fend + N);
    int* rowptr = cnt + N;
    int* cursor = rowptr + N + 1;
    int* colarr = cursor + N;
    int* part   = colarr + E;
    const int P = (N + 1023) / 1024;

    float* emb_out;
    float* logp_out;
    float* extra = fend;
    if (out_size >= N * (HID + OUTC)) {
        emb_out  = (float*)d_out;
        logp_out = (float*)d_out + (size_t)N * HID;
    } else if (out_size == N * OUTC) {
        emb_out  = extra;
        logp_out = (float*)d_out;
    } else {
        emb_out  = (float*)d_out;
        logp_out = extra;
    }

    dim3 g2(2, (N + 127) / 128);

    // Launch order puts the first mma_gemm at index 5 so ncu -s 5 -c 1 captures it.
    conv_kernel<<<(N + 3) / 4, 288>>>(x, conv_w, conv_b, bd, h0, N);            // 0
    cudaMemsetAsync(cnt, 0, (size_t)N * sizeof(int));                           // 1
    cudaMemsetAsync(cursor, 0, (size_t)N * sizeof(int));                        // 2
    hist_kernel<<<(E + 255) / 256, 256>>>(ei, cnt, E, N);                       // 3
    scan_pass1<<<P, 256>>>(cnt, part, N);                                       // 4

    mma_gemm<<<g2, 256>>>(h0, lin_self_w, LIN_DIM, nullptr, nullptr, 0,         // 5 <- ncu
                          lin_self_b, h, N, HID);
    mma_gemm<<<g2, 256>>>(h0, lin_w, LIN_DIM, nullptr, nullptr, 0,              // 6
                          lin_b, tmp, N, HID);

    scan_pass2<<<1, 64>>>(part, P, rowptr, N, E);
    scan_pass3<<<P, 256>>>(cnt, part, rowptr, N);
    fill_col<<<(E + 255) / 256, 256>>>(ei, rowptr, cursor, colarr, E, N);

    // h += gather_sum(tmp)
    gather_kernel<<<(N + 3) / 4, 256>>>(tmp, rowptr, colarr, h, 0, N);

    // three SAGE layers: gather-mean then fused dual GEMM (K=256+256)
    for (int i = 0; i < 3; i++) {
        gather_kernel<<<(N + 3) / 4, 256>>>(h, rowptr, colarr, agg, 1, N);
        float* outb = (i == 2) ? emb_out : tmp;
        mma_gemm<<<g2, 256>>>(agg, sage_l_w + (size_t)i * HID * HID, HID,
                              h,   sage_r_w + (size_t)i * HID * HID, HID,
                              sage_l_b + (size_t)i * HID, outb, N, HID);
        relu_ln_kernel<<<N, 256>>>(outb, h, ln_g + (size_t)i * HID,
                                   ln_beta + (size_t)i * HID, (i < 2) ? 1 : 0);
    }

    // MLP head + log_softmax
    mma_gemm<<<g2, 256>>>(h, mp1_w, HID, nullptr, nullptr, 0, mp1_b, z, N, HID);
    head_kernel<<<(N + 7) / 8, 256>>>(z, mp2_w, mp2_b, logp_out, N);
}

// round 16
// speedup vs baseline: 1.0779x; 1.0779x over previous
#include <cuda_runtime.h>
#include <cstdint>
#include <cstddef>

#define HID 256
#define LIN_DIM 652
#define OUTC 5

// Scratch floats: h0 (N*652) + h + tmp + agg + z (each N*256) + spill (N)
// plus int region for CSR: cnt(N) rowptr(N+1) cursor(N) col(E) part(P)
__device__ __align__(256) float g_scratch[85000000];

// ---------------------------------------------------------------------------
// Conv 3x3 VALID (8->8 ch, 11x11 -> 9x9) + flatten + concat bd_pred + relu
// ---------------------------------------------------------------------------
__global__ __launch_bounds__(288)
void conv_kernel(const float* __restrict__ x, const float* __restrict__ w,
                 const float* __restrict__ cb, const float* __restrict__ bd,
                 float* __restrict__ h0, int N)
{
    __shared__ float sx[4][968];
    __shared__ float sw[576];
    __shared__ float sb[8];
    const int tid = threadIdx.x;
    const int node0 = blockIdx.x * 4;

    for (int i = tid; i < 576; i += 288) sw[i] = w[i];
    if (tid < 8) sb[tid] = cb[tid];
    for (int i = tid; i < 4 * 968; i += 288) {
        int ln = i / 968;
        int off = i - ln * 968;
        int n = node0 + ln;
        sx[ln][off] = (n < N) ? x[(size_t)n * 968 + off] : 0.f;
    }
    __syncthreads();

    const int ln = tid / 72;
    const int t  = tid - ln * 72;
    const int n  = node0 + ln;
    if (n >= N) return;
    const int co = t / 9;
    const int io = t - co * 9;

    float acc[9];
#pragma unroll
    for (int j = 0; j < 9; j++) acc[j] = sb[co];

#pragma unroll
    for (int ci = 0; ci < 8; ci++) {
#pragma unroll
        for (int di = 0; di < 3; di++) {
            const float* xr = &sx[ln][ci * 121 + (io + di) * 11];
            const int wbase = ((co * 8 + ci) * 3 + di) * 3;
            const float w0 = sw[wbase + 0];
            const float w1 = sw[wbase + 1];
            const float w2 = sw[wbase + 2];
            float xv[11];
#pragma unroll
            for (int q = 0; q < 11; q++) xv[q] = xr[q];
#pragma unroll
            for (int j = 0; j < 9; j++)
                acc[j] += xv[j] * w0 + xv[j + 1] * w1 + xv[j + 2] * w2;
        }
    }

    float* op = h0 + (size_t)n * LIN_DIM + co * 81 + io * 9;
#pragma unroll
    for (int j = 0; j < 9; j++) op[j] = fmaxf(acc[j], 0.f);

    if (t < 4)
        h0[(size_t)n * LIN_DIM + 648 + t] = fmaxf(bd[(size_t)n * 4 + t], 0.f);
}

// ---------------------------------------------------------------------------
// Tensor-core GEMM with 2-term bf16 split (hi+lo), fp32 accumulate.
//   C[M,Nout] = A0 @ W0^T [K0] + A1 @ W1^T [K1, optional] + bias
// Block 128x128, BK=16, 512 threads / 16 warps (warp tile 32x32) for
// occupancy: ~100 regs/thread -> 16 warps/SM (vs 8 before).
// acc += Ahi*Bhi + Ahi*Blo + Alo*Bhi  (lo*lo dropped, ~2^-34)
// Fragment smem layout identical to the R9-passing kernel (scalar LDS).
// ---------------------------------------------------------------------------
#define BM 128
#define BN 128
#define SSTR 136

__device__ __forceinline__ void f32_to_bf16x2_pair(uint32_t& hi, uint32_t& lo,
                                                   float f0, float f1)
{
    uint32_t h;
    asm("cvt.rn.bf16x2.f32 %0, %1, %2;" : "=r"(h) : "f"(f1), "f"(f0));
    const float h0 = __uint_as_float(h << 16);
    const float h1 = __uint_as_float(h & 0xffff0000u);
    const float s0 = f0 - h0;
    const float s1 = f1 - h1;
    asm("cvt.rn.bf16x2.f32 %0, %1, %2;" : "=r"(lo) : "f"(s1), "f"(s0));
    hi = h;
}

__device__ __forceinline__ void mma_bf16(float* c, const uint32_t* a, const uint32_t* b)
{
    asm volatile(
        "mma.sync.aligned.m16n8k16.row.col.f32.bf16.bf16.f32 "
        "{%0,%1,%2,%3}, {%4,%5,%6,%7}, {%8,%9}, {%0,%1,%2,%3};"
        : "+f"(c[0]), "+f"(c[1]), "+f"(c[2]), "+f"(c[3])
        : "r"(a[0]), "r"(a[1]), "r"(a[2]), "r"(a[3]), "r"(b[0]), "r"(b[1]));
}

__global__ __launch_bounds__(512)
void mma_gemm(const float* __restrict__ A0, const float* __restrict__ W0, int K0,
              const float* __restrict__ A1, const float* __restrict__ W1, int K1,
              const float* __restrict__ bias,
              float* __restrict__ C, int M, int Nout)
{
    __shared__ uint32_t AsH[2][8][SSTR];
    __shared__ uint32_t AsL[2][8][SSTR];
    __shared__ uint32_t BsH[2][8][SSTR];
    __shared__ uint32_t BsL[2][8][SSTR];

    const int tid  = threadIdx.x;
    const int row0 = blockIdx.y * BM;
    const int col0 = blockIdx.x * BN;
    const int wid  = tid >> 5;          // 0..15
    const int lane = tid & 31;
    const int wm   = (wid & 3) * 32;    // warp m-offset
    const int wn   = (wid >> 2) * 32;   // warp n-offset
    const int g    = lane >> 2;
    const int tg   = lane & 3;

    float acc[2][4][4];
#pragma unroll
    for (int t = 0; t < 2; t++)
#pragma unroll
        for (int u = 0; u < 4; u++)
#pragma unroll
            for (int q = 0; q < 4; q++) acc[t][u][q] = 0.f;

    const int nc0 = (K0 + 15) >> 4;
    const int nc1 = (K1 + 15) >> 4;
    const int nch = nc0 + nc1;

    float2 ra[2], rb[2];

    auto load_global = [&](int c) {
        const bool seg1 = (c >= nc0);
        const float* A = seg1 ? A1 : A0;
        const float* W = seg1 ? W1 : W0;
        const int K  = seg1 ? K1 : K0;
        const int k0 = (seg1 ? (c - nc0) : c) << 4;
#pragma unroll
        for (int i = 0; i < 2; i++) {
            const int p  = tid + i * 512;       // 0..1023
            const int r  = p >> 3;
            const int k2 = p & 7;
            const int k  = k0 + (k2 << 1);
            float2 va = make_float2(0.f, 0.f);
            const int grow = row0 + r;
            if (grow < M && k < K)
                va = *(const float2*)&A[(size_t)grow * K + k];
            ra[i] = va;
            float2 vb = make_float2(0.f, 0.f);
            if (k < K)
                vb = *(const float2*)&W[(size_t)(col0 + r) * K + k];
            rb[i] = vb;
        }
    };

    auto convert_store = [&](int b) {
#pragma unroll
        for (int i = 0; i < 2; i++) {
            const int p  = tid + i * 512;
            const int r  = p >> 3;
            const int k2 = p & 7;
            uint32_t hi, lo;
            f32_to_bf16x2_pair(hi, lo, ra[i].x, ra[i].y);
            AsH[b][k2][r] = hi;
            AsL[b][k2][r] = lo;
            f32_to_bf16x2_pair(hi, lo, rb[i].x, rb[i].y);
            BsH[b][k2][r] = hi;
            BsL[b][k2][r] = lo;
        }
    };

    auto compute = [&](int b) {
        uint32_t ah[2][4], al[2][4], bh[4][2], bl[4][2];
#pragma unroll
        for (int t = 0; t < 2; t++) {
            const int base = wm + t * 16 + g;
            ah[t][0] = AsH[b][tg][base];
            ah[t][1] = AsH[b][tg][base + 8];
            ah[t][2] = AsH[b][tg + 4][base];
            ah[t][3] = AsH[b][tg + 4][base + 8];
            al[t][0] = AsL[b][tg][base];
            al[t][1] = AsL[b][tg][base + 8];
            al[t][2] = AsL[b][tg + 4][base];
            al[t][3] = AsL[b][tg + 4][base + 8];
        }
#pragma unroll
        for (int u = 0; u < 4; u++) {
            const int bn = wn + u * 8 + g;
            bh[u][0] = BsH[b][tg][bn];
            bh[u][1] = BsH[b][tg + 4][bn];
            bl[u][0] = BsL[b][tg][bn];
            bl[u][1] = BsL[b][tg + 4][bn];
        }
#pragma unroll
        for (int t = 0; t < 2; t++)
#pragma unroll
            for (int u = 0; u < 4; u++) {
                mma_bf16(acc[t][u], ah[t], bh[u]);
                mma_bf16(acc[t][u], ah[t], bl[u]);
                mma_bf16(acc[t][u], al[t], bh[u]);
            }
    };

    load_global(0);
    convert_store(0);
    __syncthreads();

    int buf = 0;
    for (int c = 1; c < nch; c++) {
        load_global(c);
        compute(buf);
        convert_store(buf ^ 1);
        __syncthreads();
        buf ^= 1;
    }
    compute(buf);

#pragma unroll
    for (int t = 0; t < 2; t++) {
        const int r_ = row0 + wm + t * 16 + g;
#pragma unroll
        for (int u = 0; u < 4; u++) {
            const int c_ = col0 + wn + u * 8 + 2 * tg;
            float b0 = 0.f, b1 = 0.f;
            if (bias) { b0 = bias[c_]; b1 = bias[c_ + 1]; }
            if (r_ < M) {
                float2 v = make_float2(acc[t][u][0] + b0, acc[t][u][1] + b1);
                *(float2*)&C[(size_t)r_ * Nout + c_] = v;
            }
            if (r_ + 8 < M) {
                float2 v = make_float2(acc[t][u][2] + b0, acc[t][u][3] + b1);
                *(float2*)&C[(size_t)(r_ + 8) * Nout + c_] = v;
            }
        }
    }
}

// ---------------------------------------------------------------------------
// CSR build: histogram -> 3-phase exclusive scan -> cursor fill
// ---------------------------------------------------------------------------
__global__ void hist_kernel(const int* __restrict__ ei, int* __restrict__ cnt,
                            int E, int N)
{
    const int e = blockIdx.x * blockDim.x + threadIdx.x;
    if (e >= E) return;
    const int d = ei[E + e];
    if ((unsigned)d < (unsigned)N) atomicAdd(&cnt[d], 1);
}

__global__ void scan_pass1(const int* __restrict__ cnt, int* __restrict__ part, int N)
{
    __shared__ int sh[256];
    const int b = blockIdx.x, t = threadIdx.x;
    const int base = b * 1024;
    int s = 0;
#pragma unroll
    for (int i = 0; i < 4; i++) {
        const int idx = base + t * 4 + i;
        if (idx < N) s += cnt[idx];
    }
    sh[t] = s;
    __syncthreads();
    for (int off = 128; off; off >>= 1) {
        if (t < off) sh[t] += sh[t + off];
        __syncthreads();
    }
    if (t == 0) part[b] = sh[0];
}

__global__ void scan_pass2(int* __restrict__ part, int P,
                           int* __restrict__ rowptr, int N, int E)
{
    const int t = threadIdx.x;
    if (P <= 64) {
        __shared__ int sh[64];
        int v = (t < P) ? part[t] : 0;
        sh[t] = v;
        __syncthreads();
        for (int off = 1; off < 64; off <<= 1) {
            const int x = (t >= off) ? sh[t - off] : 0;
            __syncthreads();
            sh[t] += x;
            __syncthreads();
        }
        if (t < P) part[t] = sh[t] - v;
        if (t == 0) rowptr[N] = E;
    } else if (t == 0) {
        int run = 0;
        for (int i = 0; i < P; i++) { const int v = part[i]; part[i] = run; run += v; }
        rowptr[N] = E;
    }
}

__global__ void scan_pass3(const int* __restrict__ cnt, const int* __restrict__ part,
                           int* __restrict__ rowptr, int N)
{
    __shared__ int sh[256];
    const int b = blockIdx.x, t = threadIdx.x;
    const int base = b * 1024;
    int v[4];
    int s = 0;
#pragma unroll
    for (int i = 0; i < 4; i++) {
        const int idx = base + t * 4 + i;
        v[i] = (idx < N) ? cnt[idx] : 0;
        s += v[i];
    }
    sh[t] = s;
    __syncthreads();
    for (int off = 1; off < 256; off <<= 1) {
        const int x = (t >= off) ? sh[t - off] : 0;
        __syncthreads();
        sh[t] += x;
        __syncthreads();
    }
    int excl = (t ? sh[t - 1] : 0) + part[b];
#pragma unroll
    for (int i = 0; i < 4; i++) {
        const int idx = base + t * 4 + i;
        if (idx < N) { rowptr[idx] = excl; excl += v[i]; }
    }
}

__global__ void fill_col(const int* __restrict__ ei, const int* __restrict__ rowptr,
                         int* __restrict__ cursor, int* __restrict__ col, int E, int N)
{
    const int e = blockIdx.x * blockDim.x + threadIdx.x;
    if (e >= E) return;
    const int s = ei[e];
    const int d = ei[E + e];
    if ((unsigned)s >= (unsigned)N || (unsigned)d >= (unsigned)N) return;
    const int pos = rowptr[d] + atomicAdd(&cursor[d], 1);
    col[pos] = s;
}

// ---------------------------------------------------------------------------
// CSR gather aggregation (float4-vectorized). 4 rows/block, 64 thr/row.
// ---------------------------------------------------------------------------
__global__ __launch_bounds__(256)
void gather_kernel(const float* __restrict__ feat,
                   const int* __restrict__ rowptr,
                   const int* __restrict__ col,
                   float* __restrict__ out, int mode, int N)
{
    const int r = blockIdx.x * 4 + (threadIdx.x >> 6);
    const int t = threadIdx.x & 63;
    if (r >= N) return;
    const int beg = rowptr[r], end = rowptr[r + 1];

    float4 s = make_float4(0.f, 0.f, 0.f, 0.f);
    int e = beg;
    for (; e + 1 < end; e += 2) {
        const int s0 = col[e], s1 = col[e + 1];
        const float4 v0 = ((const float4*)(feat + (size_t)s0 * HID))[t];
        const float4 v1 = ((const float4*)(feat + (size_t)s1 * HID))[t];
        s.x += v0.x + v1.x;
        s.y += v0.y + v1.y;
        s.z += v0.z + v1.z;
        s.w += v0.w + v1.w;
    }
    if (e < end) {
        const float4 v = ((const float4*)(feat + (size_t)col[e] * HID))[t];
        s.x += v.x; s.y += v.y; s.z += v.z; s.w += v.w;
    }

    float4* op = (float4*)(out + (size_t)r * HID) + t;
    if (mode) {
        const int d = end - beg;
        const float inv = 1.f / (float)(d > 0 ? d : 1);
        *op = make_float4(s.x * inv, s.y * inv, s.z * inv, s.w * inv);
    } else {
        const float4 o = *op;
        *op = make_float4(o.x + s.x, o.y + s.y, o.z + s.z, o.w + s.w);
    }
}

// ---------------------------------------------------------------------------
// relu (+ optional layernorm over HID=256). One block (256 threads) per row.
// ---------------------------------------------------------------------------
__global__ void relu_ln_kernel(const float* __restrict__ in, float* __restrict__ out,
                               const float* __restrict__ gamma, const float* __restrict__ beta,
                               int doLN)
{
    const int r = blockIdx.x;
    const int t = threadIdx.x;
    const size_t idx = (size_t)r * HID + t;
    const float v = fmaxf(in[idx], 0.f);
    if (!doLN) { out[idx] = v; return; }

    float s = v, s2 = v * v;
#pragma unroll
    for (int off = 16; off; off >>= 1) {
        s  += __shfl_xor_sync(0xffffffffu, s, off);
        s2 += __shfl_xor_sync(0xffffffffu, s2, off);
    }
    __shared__ float sh[16];
    const int wid = t >> 5, lane = t & 31;
    if (lane == 0) { sh[wid] = s; sh[8 + wid] = s2; }
    __syncthreads();
    if (t == 0) {
        float S = 0.f, S2 = 0.f;
#pragma unroll
        for (int i = 0; i < 8; i++) { S += sh[i]; S2 += sh[8 + i]; }
        const float mu = S * (1.f / HID);
        const float var = S2 * (1.f / HID) - mu * mu;
        sh[0] = mu;
        sh[1] = rsqrtf(var + 1e-5f);
    }
    __syncthreads();
    const float mu = sh[0], rstd = sh[1];
    out[idx] = (v - mu) * rstd * gamma[t] + beta[t];
}

// ---------------------------------------------------------------------------
// Head: logits[5] = z @ mp2_w^T + b, then log_softmax. One warp per row.
// ---------------------------------------------------------------------------
__global__ void head_kernel(const float* __restrict__ z, const float* __restrict__ w2,
                            const float* __restrict__ b2, float* __restrict__ out, int N)
{
    const int row = blockIdx.x * 8 + (threadIdx.x >> 5);
    const int lane = threadIdx.x & 31;
    if (row >= N) return;
    const float* zr = z + (size_t)row * HID;
    float a0 = 0, a1 = 0, a2 = 0, a3 = 0, a4 = 0;
    for (int k = lane; k < HID; k += 32) {
        const float v = zr[k];
        a0 += v * w2[k];
        a1 += v * w2[256 + k];
        a2 += v * w2[512 + k];
        a3 += v * w2[768 + k];
        a4 += v * w2[1024 + k];
    }
#pragma unroll
    for (int off = 16; off; off >>= 1) {
        a0 += __shfl_xor_sync(0xffffffffu, a0, off);
        a1 += __shfl_xor_sync(0xffffffffu, a1, off);
        a2 += __shfl_xor_sync(0xffffffffu, a2, off);
        a3 += __shfl_xor_sync(0xffffffffu, a3, off);
        a4 += __shfl_xor_sync(0xffffffffu, a4, off);
    }
    if (lane == 0) {
        float l[5] = {a0 + b2[0], a1 + b2[1], a2 + b2[2], a3 + b2[3], a4 + b2[4]};
        float mx = l[0];
#pragma unroll
        for (int o = 1; o < 5; o++) mx = fmaxf(mx, l[o]);
        float se = 0.f;
#pragma unroll
        for (int o = 0; o < 5; o++) se += expf(l[o] - mx);
        const float lse = mx + logf(se);
#pragma unroll
        for (int o = 0; o < 5; o++) out[(size_t)row * 5 + o] = l[o] - lse;
    }
}

// ---------------------------------------------------------------------------
extern "C" void kernel_launch(void* const* d_in, const int* in_sizes, int n_in,
                              void* d_out, int out_size)
{
    const float* x          = (const float*)d_in[0];
    const float* bd         = (const float*)d_in[1];
    const int*   ei         = (const int*)d_in[2];   // int64 downcast to int32 by harness
    const float* conv_w     = (const float*)d_in[3];
    const float* conv_b     = (const float*)d_in[4];
    const float* lin_w      = (const float*)d_in[5];
    const float* lin_b      = (const float*)d_in[6];
    const float* lin_self_w = (const float*)d_in[7];
    const float* lin_self_b = (const float*)d_in[8];
    const float* sage_l_w   = (const float*)d_in[9];
    const float* sage_l_b   = (const float*)d_in[10];
    const float* sage_r_w   = (const float*)d_in[11];
    const float* ln_g       = (const float*)d_in[12];
    const float* ln_beta    = (const float*)d_in[13];
    const float* mp1_w      = (const float*)d_in[14];
    const float* mp1_b      = (const float*)d_in[15];
    const float* mp2_w      = (const float*)d_in[16];
    const float* mp2_b      = (const float*)d_in[17];

    const int N = in_sizes[1] / 4;   // bd_pred is [N,4]
    const int E = in_sizes[2] / 2;   // edge_index is [2,E]

    float* base = nullptr;
    cudaGetSymbolAddress((void**)&base, g_scratch);
    float* h0     = base;
    float* h      = h0  + (size_t)N * LIN_DIM;
    float* tmp    = h   + (size_t)N * HID;
    float* agg    = tmp + (size_t)N * HID;
    float* z      = agg + (size_t)N * HID;
    float* fend   = z   + (size_t)N * HID;

    int* cnt    = (int*)(fend + N);
    int* rowptr = cnt + N;
    int* cursor = rowptr + N + 1;
    int* colarr = cursor + N;
    int* part   = colarr + E;
    const int P = (N + 1023) / 1024;

    float* emb_out;
    float* logp_out;
    float* extra = fend;
    if (out_size >= N * (HID + OUTC)) {
        emb_out  = (float*)d_out;
        logp_out = (float*)d_out + (size_t)N * HID;
    } else if (out_size == N * OUTC) {
        emb_out  = extra;
        logp_out = (float*)d_out;
    } else {
        emb_out  = (float*)d_out;
        logp_out = extra;
    }

    dim3 g2(2, (N + 127) / 128);

    // Launch order puts the first mma_gemm at index 5 so ncu -s 5 -c 1 captures it.
    conv_kernel<<<(N + 3) / 4, 288>>>(x, conv_w, conv_b, bd, h0, N);            // 0
    cudaMemsetAsync(cnt, 0, (size_t)N * sizeof(int));                           // 1
    cudaMemsetAsync(cursor, 0, (size_t)N * sizeof(int));                        // 2
    hist_kernel<<<(E + 255) / 256, 256>>>(ei, cnt, E, N);                       // 3
    scan_pass1<<<P, 256>>>(cnt, part, N);                                       // 4

    mma_gemm<<<g2, 512>>>(h0, lin_self_w, LIN_DIM, nullptr, nullptr, 0,         // 5 <- ncu
                          lin_self_b, h, N, HID);
    mma_gemm<<<g2, 512>>>(h0, lin_w, LIN_DIM, nullptr, nullptr, 0,              // 6
                          lin_b, tmp, N, HID);

    scan_pass2<<<1, 64>>>(part, P, rowptr, N, E);
    scan_pass3<<<P, 256>>>(cnt, part, rowptr, N);
    fill_col<<<(E + 255) / 256, 256>>>(ei, rowptr, cursor, colarr, E, N);

    // h += gather_sum(tmp)
    gather_kernel<<<(N + 3) / 4, 256>>>(tmp, rowptr, colarr, h, 0, N);

    // three SAGE layers: gather-mean then fused dual GEMM (K=256+256)
    for (int i = 0; i < 3; i++) {
        gather_kernel<<<(N + 3) / 4, 256>>>(h, rowptr, colarr, agg, 1, N);
        float* outb = (i == 2) ? emb_out : tmp;
        mma_gemm<<<g2, 512>>>(agg, sage_l_w + (size_t)i * HID * HID, HID,
                              h,   sage_r_w + (size_t)i * HID * HID, HID,
                              sage_l_b + (size_t)i * HID, outb, N, HID);
        relu_ln_kernel<<<N, 256>>>(outb, h, ln_g + (size_t)i * HID,
                                   ln_beta + (size_t)i * HID, (i < 2) ? 1 : 0);
    }

    // MLP head + log_softmax
    mma_gemm<<<g2, 512>>>(h, mp1_w, HID, nullptr, nullptr, 0, mp1_b, z, N, HID);
    head_kernel<<<(N + 7) / 8, 256>>>(z, mp2_w, mp2_b, logp_out, N);
}